// round 12
// baseline (speedup 1.0000x reference)
#include <cuda_runtime.h>
#include <cuda_bf16.h>

#define FULL_MASK 0xFFFFFFFFu

// gram index for (i,j), i<=j, nv=5 -> linear index in s[15]
__device__ __forceinline__ constexpr int sidx(int i, int j) {
    return (i == 0 ? 0 : i == 1 ? 5 : i == 2 ? 9 : i == 3 ? 12 : 14) + (j - i);
}

// pair index for (i,j), i<j, nv=5 -> 0..9 in reference order
__device__ __forceinline__ constexpr int pidx(int i, int j) {
    return (i == 0 ? 0 : i == 1 ? 3 : i == 2 ? 5 : 6) + (j - 1);
}

// Prefetch distance in quads (~1 resident wave ahead; 3072 quads = 30 MB in L2)
#define PF_DIST 3072

__global__ void __launch_bounds__(128, 5)
cm_validator_kernel(const float* __restrict__ verts,
                    float* __restrict__ out_pairs,   // (B, 10)
                    float* __restrict__ out_vol,     // (B,)
                    int B)
{
    const int warp = blockIdx.x * (blockDim.x >> 5) + (threadIdx.x >> 5);
    const int lane = threadIdx.x & 31;
    const int grp  = lane >> 3;        // 4 batches per warp
    const int sub  = lane & 7;         // 8 lanes x 16 dims per batch
    const int batch = warp * 4 + grp;
    if (batch >= B) return;

    // Batch layout: 5 vertices x 128 floats contiguous = 160 float4.
    // Lane covers float4 chunks {sub + 8c : c=0..3} of each vertex row, so
    // for each (vertex, chunk) the 8 lanes of a group touch one contiguous
    // 128B segment. All 20 loads are front-batched (MLP_p1 = 20).
    const float4* vp = reinterpret_cast<const float4*>(verts)
                       + (size_t)batch * 160 + sub;

    float4 v[5][4];
#pragma unroll
    for (int i = 0; i < 5; i++) {
#pragma unroll
        for (int c = 0; c < 4; c++) {
            v[i][c] = __ldcs(vp + i * 32 + c * 8);
        }
    }

    // L2 prefetch for the quad one wave ahead: 10 KB = 80 x 128B lines,
    // covered by lanes {lane, lane+32, lane+64} (third set predicated).
    {
        const int nquads = B >> 2;
        const int pfq = warp + PF_DIST;
        if (pfq < nquads) {
            const char* pbase = reinterpret_cast<const char*>(verts)
                                + (size_t)pfq * 10240;
            asm volatile("prefetch.global.L2 [%0];" :: "l"(pbase + lane * 128));
            asm volatile("prefetch.global.L2 [%0];" :: "l"(pbase + (lane + 32) * 128));
            if (lane < 16) {
                asm volatile("prefetch.global.L2 [%0];" :: "l"(pbase + (lane + 64) * 128));
            }
        }
    }

    // 15 partial dot products (i<=j) over this lane's 16 dims.
    float s[15];
    {
        int t = 0;
#pragma unroll
        for (int i = 0; i < 5; i++) {
#pragma unroll
            for (int j = i; j < 5; j++) {
                float acc = v[i][0].x * v[j][0].x;
#pragma unroll
                for (int c = 0; c < 4; c++) {
                    if (c > 0) acc = fmaf(v[i][c].x, v[j][c].x, acc);
                    acc = fmaf(v[i][c].y, v[j][c].y, acc);
                    acc = fmaf(v[i][c].z, v[j][c].z, acc);
                    acc = fmaf(v[i][c].w, v[j][c].w, acc);
                }
                s[t++] = acc;
            }
        }
    }

    // Butterfly all-reduce within each 8-lane group: 3 rounds x 15 shfl.
#pragma unroll
    for (int m = 4; m > 0; m >>= 1) {
#pragma unroll
        for (int p = 0; p < 15; p++) {
            s[p] += __shfl_xor_sync(FULL_MASK, s[p], m);
        }
    }

    // Squared distances for the 10 pairs (upper triangle), reference order.
    float nrm[5] = {s[sidx(0,0)], s[sidx(1,1)], s[sidx(2,2)],
                    s[sidx(3,3)], s[sidx(4,4)]};

    float d2[10];
#pragma unroll
    for (int i = 0; i < 5; i++) {
#pragma unroll
        for (int j = i + 1; j < 5; j++) {
            const float g = s[sidx(i, j)];
            d2[pidx(i, j)] = fmaxf(fmaf(-2.0f, g, nrm[i] + nrm[j]), 0.0f);
        }
    }

    // Cayley-Menger determinant reduced exactly (two unit-pivot eliminations)
    // to a symmetric 4x4:  P[a][b] = D[a+1][b+1] - D[0][b+1] - D[0][a+1]
    // vol2 = PREFACTOR * det(CM) = det(P) / 9216.
    const float p00 = -2.0f * d2[pidx(0,1)];
    const float p11 = -2.0f * d2[pidx(0,2)];
    const float p22 = -2.0f * d2[pidx(0,3)];
    const float p33 = -2.0f * d2[pidx(0,4)];
    const float p01 = d2[pidx(1,2)] - d2[pidx(0,2)] - d2[pidx(0,1)];
    const float p02 = d2[pidx(1,3)] - d2[pidx(0,3)] - d2[pidx(0,1)];
    const float p03 = d2[pidx(1,4)] - d2[pidx(0,4)] - d2[pidx(0,1)];
    const float p12 = d2[pidx(2,3)] - d2[pidx(0,3)] - d2[pidx(0,2)];
    const float p13 = d2[pidx(2,4)] - d2[pidx(0,4)] - d2[pidx(0,2)];
    const float p23 = d2[pidx(3,4)] - d2[pidx(0,4)] - d2[pidx(0,3)];

    // det of symmetric 4x4 via 2x2 minors (rows 0,1 vs rows 2,3); c0 == s5.
    const float s0 = p00 * p11 - p01 * p01;
    const float s1 = p00 * p12 - p02 * p01;
    const float s2 = p00 * p13 - p03 * p01;
    const float s3 = p01 * p12 - p02 * p11;
    const float s4 = p01 * p13 - p03 * p11;
    const float s5 = p02 * p13 - p03 * p12;

    const float c1 = p02 * p23 - p22 * p03;
    const float c2 = p02 * p33 - p23 * p03;
    const float c3 = p12 * p23 - p22 * p13;
    const float c4 = p12 * p33 - p23 * p13;
    const float c5 = p22 * p33 - p23 * p23;

    const float det4 = s0 * c5 - s1 * c4 + s2 * c3 + s3 * c2 - s4 * c1 + s5 * s5;
    const float vol2 = det4 * (1.0f / 9216.0f);

    // Select this lane's pair value (lanes sub=0..7 own pairs 0..7; the
    // remaining two pairs are written by sub=0,1 at offset +8).
    float pv = d2[0];
    pv = (sub == 1) ? d2[1] : pv;
    pv = (sub == 2) ? d2[2] : pv;
    pv = (sub == 3) ? d2[3] : pv;
    pv = (sub == 4) ? d2[4] : pv;
    pv = (sub == 5) ? d2[5] : pv;
    pv = (sub == 6) ? d2[6] : pv;
    pv = (sub == 7) ? d2[7] : pv;
    float pv2 = (sub == 0) ? d2[8] : d2[9];

    float* op = out_pairs + (size_t)batch * 10;
    op[sub] = pv;
    if (sub < 2) {
        op[8 + sub] = pv2;
    }
    if (sub == 0) {
        out_vol[batch] = vol2;
    }
}

extern "C" void kernel_launch(void* const* d_in, const int* in_sizes, int n_in,
                              void* d_out, int out_size) {
    const float* verts = (const float*)d_in[0];
    const int B = in_sizes[0] / 640;   // (B, 5, 128) float32

    float* out = (float*)d_out;
    float* out_pairs = out;                      // (B, 10) flattened first
    float* out_vol   = out + (size_t)B * 10;     // (B,) concatenated after

    const int warps_needed = (B + 3) / 4;        // 4 batches per warp
    const int warps_per_block = 4;               // 128 threads
    const int blocks = (warps_needed + warps_per_block - 1) / warps_per_block;
    cm_validator_kernel<<<blocks, 128>>>(verts, out_pairs, out_vol, B);
}

// round 15
// speedup vs baseline: 1.0462x; 1.0462x over previous
#include <cuda_runtime.h>
#include <cuda_bf16.h>

#define FULL_MASK 0xFFFFFFFFu

// gram index for (i,j), i<=j, nv=5 -> linear index in s[15]
__device__ __forceinline__ constexpr int sidx(int i, int j) {
    return (i == 0 ? 0 : i == 1 ? 5 : i == 2 ? 9 : i == 3 ? 12 : 14) + (j - i);
}

// pair index for (i,j), i<j, nv=5 -> 0..9 in reference order
__device__ __forceinline__ constexpr int pidx(int i, int j) {
    return (i == 0 ? 0 : i == 1 ? 3 : i == 2 ? 5 : 6) + (j - 1);
}

__global__ void __launch_bounds__(128, 5)
cm_validator_kernel(const float* __restrict__ verts,
                    float* __restrict__ out_pairs,   // (B, 10)
                    float* __restrict__ out_vol,     // (B,)
                    int B)
{
    const int warp = blockIdx.x * (blockDim.x >> 5) + (threadIdx.x >> 5);
    const int lane = threadIdx.x & 31;
    const int grp  = lane >> 3;        // 4 batches per warp
    const int sub  = lane & 7;         // 8 lanes x 16 dims per batch
    const int batch = warp * 4 + grp;
    if (batch >= B) return;

    // Batch layout: 5 vertices x 128 floats contiguous = 160 float4.
    // Lane covers float4 chunks {sub + 8c : c=0..3} of each vertex row, so
    // for each (vertex, chunk) the 8 lanes of a group touch one contiguous
    // 128B segment. All 20 loads are front-batched (MLP_p1 = 20).
    const float4* vp = reinterpret_cast<const float4*>(verts)
                       + (size_t)batch * 160 + sub;

    float4 v[5][4];
#pragma unroll
    for (int i = 0; i < 5; i++) {
#pragma unroll
        for (int c = 0; c < 4; c++) {
            v[i][c] = __ldcs(vp + i * 32 + c * 8);
        }
    }

    // 15 partial dot products (i<=j) over this lane's 16 dims.
    float s[15];
    {
        int t = 0;
#pragma unroll
        for (int i = 0; i < 5; i++) {
#pragma unroll
            for (int j = i; j < 5; j++) {
                float acc = v[i][0].x * v[j][0].x;
#pragma unroll
                for (int c = 0; c < 4; c++) {
                    if (c > 0) acc = fmaf(v[i][c].x, v[j][c].x, acc);
                    acc = fmaf(v[i][c].y, v[j][c].y, acc);
                    acc = fmaf(v[i][c].z, v[j][c].z, acc);
                    acc = fmaf(v[i][c].w, v[j][c].w, acc);
                }
                s[t++] = acc;
            }
        }
    }

    // Butterfly all-reduce within each 8-lane group: 3 rounds x 15 shfl.
#pragma unroll
    for (int m = 4; m > 0; m >>= 1) {
#pragma unroll
        for (int p = 0; p < 15; p++) {
            s[p] += __shfl_xor_sync(FULL_MASK, s[p], m);
        }
    }

    // Squared distances for the 10 pairs (upper triangle), reference order.
    float nrm[5] = {s[sidx(0,0)], s[sidx(1,1)], s[sidx(2,2)],
                    s[sidx(3,3)], s[sidx(4,4)]};

    float d2[10];
#pragma unroll
    for (int i = 0; i < 5; i++) {
#pragma unroll
        for (int j = i + 1; j < 5; j++) {
            const float g = s[sidx(i, j)];
            d2[pidx(i, j)] = fmaxf(fmaf(-2.0f, g, nrm[i] + nrm[j]), 0.0f);
        }
    }

    // Cayley-Menger determinant reduced exactly (two unit-pivot eliminations)
    // to a symmetric 4x4:  P[a][b] = D[a+1][b+1] - D[0][b+1] - D[0][a+1]
    // vol2 = PREFACTOR * det(CM) = det(P) / 9216.
    const float p00 = -2.0f * d2[pidx(0,1)];
    const float p11 = -2.0f * d2[pidx(0,2)];
    const float p22 = -2.0f * d2[pidx(0,3)];
    const float p33 = -2.0f * d2[pidx(0,4)];
    const float p01 = d2[pidx(1,2)] - d2[pidx(0,2)] - d2[pidx(0,1)];
    const float p02 = d2[pidx(1,3)] - d2[pidx(0,3)] - d2[pidx(0,1)];
    const float p03 = d2[pidx(1,4)] - d2[pidx(0,4)] - d2[pidx(0,1)];
    const float p12 = d2[pidx(2,3)] - d2[pidx(0,3)] - d2[pidx(0,2)];
    const float p13 = d2[pidx(2,4)] - d2[pidx(0,4)] - d2[pidx(0,2)];
    const float p23 = d2[pidx(3,4)] - d2[pidx(0,4)] - d2[pidx(0,3)];

    // det of symmetric 4x4 via 2x2 minors (rows 0,1 vs rows 2,3); c0 == s5.
    const float s0 = p00 * p11 - p01 * p01;
    const float s1 = p00 * p12 - p02 * p01;
    const float s2 = p00 * p13 - p03 * p01;
    const float s3 = p01 * p12 - p02 * p11;
    const float s4 = p01 * p13 - p03 * p11;
    const float s5 = p02 * p13 - p03 * p12;

    const float c1 = p02 * p23 - p22 * p03;
    const float c2 = p02 * p33 - p23 * p03;
    const float c3 = p12 * p23 - p22 * p13;
    const float c4 = p12 * p33 - p23 * p13;
    const float c5 = p22 * p33 - p23 * p23;

    const float det4 = s0 * c5 - s1 * c4 + s2 * c3 + s3 * c2 - s4 * c1 + s5 * s5;
    const float vol2 = det4 * (1.0f / 9216.0f);

    // Select this lane's pair value (lanes sub=0..7 own pairs 0..7; the
    // remaining two pairs are written by sub=0,1 at offset +8).
    float pv = d2[0];
    pv = (sub == 1) ? d2[1] : pv;
    pv = (sub == 2) ? d2[2] : pv;
    pv = (sub == 3) ? d2[3] : pv;
    pv = (sub == 4) ? d2[4] : pv;
    pv = (sub == 5) ? d2[5] : pv;
    pv = (sub == 6) ? d2[6] : pv;
    pv = (sub == 7) ? d2[7] : pv;
    float pv2 = (sub == 0) ? d2[8] : d2[9];

    // Streaming (evict-first) stores: outputs are write-once, keep them from
    // displacing the read stream in L2.
    float* op = out_pairs + (size_t)batch * 10;
    __stcs(op + sub, pv);
    if (sub < 2) {
        __stcs(op + 8 + sub, pv2);
    }
    if (sub == 0) {
        __stcs(out_vol + batch, vol2);
    }
}

extern "C" void kernel_launch(void* const* d_in, const int* in_sizes, int n_in,
                              void* d_out, int out_size) {
    const float* verts = (const float*)d_in[0];
    const int B = in_sizes[0] / 640;   // (B, 5, 128) float32

    float* out = (float*)d_out;
    float* out_pairs = out;                      // (B, 10) flattened first
    float* out_vol   = out + (size_t)B * 10;     // (B,) concatenated after

    const int warps_needed = (B + 3) / 4;        // 4 batches per warp
    const int warps_per_block = 4;               // 128 threads
    const int blocks = (warps_needed + warps_per_block - 1) / warps_per_block;
    cm_validator_kernel<<<blocks, 128>>>(verts, out_pairs, out_vol, B);
}